// round 10
// baseline (speedup 1.0000x reference)
#include <cuda_runtime.h>

#define N 128
#define BATCH 32
#define NITERS 500
#define RHO 0.1f
#define SIGMA 1e-6f
#define RELAX 1.6f
#define ALPHA 0.5f
#define DELTA 10.0f

typedef unsigned long long ull;

union F2U { ull u; float2 f; };
__device__ __forceinline__ ull pack2(float x, float y) { F2U u; u.f = make_float2(x, y); return u.u; }
__device__ __forceinline__ ull fma2(ull a, ull b, ull c) {
    ull d; asm("fma.rn.f32x2 %0, %1, %2, %3;" : "=l"(d) : "l"(a), "l"(b), "l"(c)); return d;
}
__device__ __forceinline__ ull add2(ull a, ull b) {
    ull d; asm("add.rn.f32x2 %0, %1, %2;" : "=l"(d) : "l"(a), "l"(b)); return d;
}
__device__ __forceinline__ ull mul2(ull a, ull b) {
    ull d; asm("mul.rn.f32x2 %0, %1, %2;" : "=l"(d) : "l"(a), "l"(b)); return d;
}

// dd buffers per item: rows 0-63 at p*64, rows 64-127 at 132+p*64 (bank skew).
// Item B's pool starts at float offset 264.
#define DD_A(p) ((p) * 64)
#define DD_B(p) (132 + (p) * 64)
#define ITEM_OFF 264

// 288 threads, grid = BATCH/2. Each CTA solves TWO batch items with one set of
// W registers (warps 0-7) — the two ADMM streams are independent, giving each
// warp 2x ILP to fill latency bubbles. Warp 8: two 16-lane scalar-row solvers.
__global__ void __launch_bounds__(288, 1)
mvo_kernel(const float* __restrict__ X, const float* __restrict__ V,
           const float* __restrict__ beta, const float* __restrict__ thE,
           const float* __restrict__ thD, const float* __restrict__ lg1,
           const float* __restrict__ lg2, const float* __restrict__ bvec,
           const float* __restrict__ hvec, float* __restrict__ out) {
    __shared__ __align__(16) float sddpool[2 * ITEM_OFF];
    __shared__ __align__(16) ull rowbuf[2][64];
    __shared__ __align__(16) float sq[N];
    __shared__ float red8[8];
    __shared__ float sQ1;
    __shared__ float c2buf[4];          // [p][item]
    __shared__ __align__(16) float sx[2 * N];

    const int tid = threadIdx.x;
    const int bA = 2 * blockIdx.x, bB = bA + 1;
    const int w = tid >> 5, l = tid & 31;
    const bool rowt = (tid < 256);
    const int j = (w & 7) * 16 + (l & 15);
    const int hf = l >> 4;

    if (tid < 128) sx[tid] = X[bA * N + tid];
    else if (tid < 256) sx[128 + (tid - 128)] = X[bB * N + (tid - 128)];
    if (tid < 4) c2buf[tid] = 0.f;
    __syncthreads();

    // ---------- per-row constants + y_pred for both items ----------
    float yp2A = 0.f, yp2B = 0.f, mpt2 = 0.f, up1 = 0.f;
    ull rr[32];
    if (rowt) {
        float accA = 0.f, accB = 0.f;
        {
            const float* xpA = sx + hf * 64;
            const float* xpB = sx + 128 + hf * 64;
            const float* bp = beta + (hf * 64) * N + j;
#pragma unroll 8
            for (int k = 0; k < 64; k++) {
                float bv = bp[k * N];
                accA = fmaf(xpA[k], bv, accA);
                accB = fmaf(xpB[k], bv, accB);
            }
        }
        float ypA = accA + __shfl_xor_sync(0xffffffffu, accA, 16);
        float ypB = accB + __shfl_xor_sync(0xffffffffu, accB, 16);
        if (hf == 0) {
            out[BATCH * N + bA * N + j] = ypA;
            out[BATCH * N + bB * N + j] = ypB;
        }
        yp2A = 2.0f * ypA;
        yp2B = 2.0f * ypB;
        const float g1v = exp10f(lg1[0]);
        const float ev  = 1.0f / (1.0f + expf(-thE[j]));
        mpt2 = -2.0f * (ALPHA * g1v * ev);
        up1 = hvec[j];

        const float g2 = exp10f(lg2[0]);
        const float sg = 1.0f / (1.0f + expf(-thD[j]));
        const float dg = 2.0f * (1.0f - ALPHA) * g2 * sg * sg + 3.0f * RHO + SIGMA;
        const float2* vrow = (const float2*)(V + j * N + hf * 64);
#pragma unroll
        for (int m = 0; m < 32; m++) {
            float2 v = vrow[m];
            float a = fmaf(2.0f * DELTA, v.x, 2.0f * RHO);
            float c = fmaf(2.0f * DELTA, v.y, 2.0f * RHO);
            int gc = hf * 64 + 2 * m;
            if (gc == j)     a += dg;
            if (gc + 1 == j) c += dg;
            rr[m] = pack2(a, c);
        }
    }

    // ---------- 128 Gauss-Jordan pivots (1 barrier each) ----------
#pragma unroll
    for (int k = 0; k < N; k++) {
        ull* buf = rowbuf[k & 1];
        if (rowt && j == k) {
            ulonglong2* buf2 = (ulonglong2*)buf;
#pragma unroll
            for (int m = 0; m < 16; m++)
                buf2[hf * 16 + m] = make_ulonglong2(rr[2 * m], rr[2 * m + 1]);
        }
        __syncthreads();
        if (rowt) {
            const float* bf = (const float*)buf;
            const float d = 1.0f / bf[k];
            const int mm = (k & 63) >> 1;
            F2U u; u.u = rr[mm];
            float fown = (k & 1) ? u.f.y : u.f.x;
            float f = __shfl_sync(0xffffffffu, fown, (l & 15) | ((k >> 6) << 4));
            const ulonglong2* bh = (const ulonglong2*)(buf + hf * 32);
            if (j == k) {
                ull d2 = pack2(d, d);
#pragma unroll
                for (int m = 0; m < 32; m++) rr[m] = mul2(rr[m], d2);
                if (hf == (k >> 6)) {
                    F2U t; t.u = rr[mm];
                    if (k & 1) t.f.y = d; else t.f.x = d;
                    rr[mm] = t.u;
                }
            } else {
                float fd = f * d;
                ull nf2 = pack2(-fd, -fd);
#pragma unroll
                for (int m = 0; m < 16; m++) {
                    ulonglong2 bb = bh[m];
                    rr[2 * m]     = fma2(nf2, bb.x, rr[2 * m]);
                    rr[2 * m + 1] = fma2(nf2, bb.y, rr[2 * m + 1]);
                }
                if (hf == (k >> 6)) {
                    F2U t; t.u = rr[mm];
                    if (k & 1) t.f.y = -fd; else t.f.x = -fd;
                    rr[mm] = t.u;
                }
            }
        }
    }

    // ---------- q = W@1, Q1 ----------
    float qj = 0.f;
    if (rowt) {
        ull s0 = 0, s1 = 0, s2 = 0, s3 = 0;
#pragma unroll
        for (int m = 0; m < 32; m += 4) {
            s0 = add2(s0, rr[m]);     s1 = add2(s1, rr[m + 1]);
            s2 = add2(s2, rr[m + 2]); s3 = add2(s3, rr[m + 3]);
        }
        F2U ts; ts.u = add2(add2(s0, s1), add2(s2, s3));
        float qh = ts.f.x + ts.f.y;
        qj = qh + __shfl_xor_sync(0xffffffffu, qh, 16);
        if (hf == 0) sq[j] = qj;
        float r = qj;
        r += __shfl_xor_sync(0xffffffffu, r, 8);
        r += __shfl_xor_sync(0xffffffffu, r, 4);
        r += __shfl_xor_sync(0xffffffffu, r, 2);
        r += __shfl_xor_sync(0xffffffffu, r, 1);
        if (l == 0) red8[w] = r;
    }
    __syncthreads();
    if (tid == 0) {
        float t = 0.f;
#pragma unroll
        for (int i = 0; i < 8; i++) t += red8[i];
        sQ1 = t;
    }

    const float omr = 1.0f - RELAX;
    const float hirs = 0.5f / (RHO + SIGMA);
    const int ddoff = (j < 64) ? j : (68 + j);     // + p*64 (+ ITEM_OFF for B)

    // initial ddl (x=z=y=0): ddl = yp2
    if (rowt && hf == 0) {
        sddpool[ddoff] = yp2A;
        sddpool[ITEM_OFF + ddoff] = yp2B;
    }
    __syncthreads();   // covers sQ1 + initial dd

    // ---------- 500-iteration ADMM, two independent streams ----------
    if (rowt) {
        const ull HALF2 = pack2(0.5f, -0.5f);
        const ull R2v   = pack2(RELAX, RELAX);
        const ull mR2   = pack2(-RELAX, -RELAX);
        const ull OMR2  = pack2(omr, omr);

        ull XpA = 0ull, XpB = 0ull;
        ull A23A = 0ull, A23B = 0ull;
        float a1rA = 0.f, a1rB = 0.f;
        float hsuA = mpt2 * hirs, hsuB = mpt2 * hirs;

#pragma unroll 2
        for (int it = 0; it < NITERS; it++) {
            const int p = it & 1;
            __syncthreads();
            float2 cc = *(const float2*)&c2buf[2 * p];

            const ulonglong2* ddsA =
                (const ulonglong2*)(sddpool + (hf ? DD_B(p) : DD_A(p)));
            const ulonglong2* ddsB =
                (const ulonglong2*)(sddpool + ITEM_OFF + (hf ? DD_B(p) : DD_A(p)));
            ull a0 = 0ull, a1 = 0ull, a2 = 0ull, a3 = 0ull;
            ull e0 = 0ull, e1 = 0ull, e2 = 0ull, e3 = 0ull;
#pragma unroll
            for (int m = 0; m < 8; m++) {
                ulonglong2 d0 = ddsA[2 * m];
                ulonglong2 d1 = ddsA[2 * m + 1];
                ulonglong2 f0 = ddsB[2 * m];
                ulonglong2 f1 = ddsB[2 * m + 1];
                a0 = fma2(rr[4 * m + 0], d0.x, a0);
                e0 = fma2(rr[4 * m + 0], f0.x, e0);
                a1 = fma2(rr[4 * m + 1], d0.y, a1);
                e1 = fma2(rr[4 * m + 1], f0.y, e1);
                a2 = fma2(rr[4 * m + 2], d1.x, a2);
                e2 = fma2(rr[4 * m + 2], f1.x, e2);
                a3 = fma2(rr[4 * m + 3], d1.y, a3);
                e3 = fma2(rr[4 * m + 3], f1.y, e3);
            }
            F2U accA; accA.u = add2(add2(a0, a1), add2(a2, a3));
            F2U accB; accB.u = add2(add2(e0, e1), add2(e2, e3));
            float thA = accA.f.x + accA.f.y;
            float thB = accB.f.x + accB.f.y;
            float tA = fmaf(cc.x, qj, thA + __shfl_xor_sync(0xffffffffu, thA, 16));
            float tB = fmaf(cc.y, qj, thB + __shfl_xor_sync(0xffffffffu, thB, 16));

            // ---- epilogue A ----
            ull XTA = fma2(HALF2, pack2(tA, tA), pack2(hsuA, hsuA));
            ull V23A = fma2(mR2, XTA, A23A);
            F2U vnA; vnA.u = V23A;
            float av2A = fabsf(vnA.f.x);
            float av3A = fabsf(vnA.f.y);
            float v1A = fmaf(-RELAX, tA, a1rA);
            float z1A = fminf(v1A, up1);
            float u1A = fmaf(2.0f, z1A, -v1A);
            float ddlA = fmaf(-2.0f * RHO, u1A, yp2A);
            ddlA = fmaf(RHO, av2A, ddlA);
            ddlA = fmaf(-RHO, av3A, ddlA);
            if (hf == 0) sddpool[(p ^ 1) * 64 + ddoff] = ddlA;

            // ---- epilogue B ----
            ull XTB = fma2(HALF2, pack2(tB, tB), pack2(hsuB, hsuB));
            ull V23B = fma2(mR2, XTB, A23B);
            F2U vnB; vnB.u = V23B;
            float av2B = fabsf(vnB.f.x);
            float av3B = fabsf(vnB.f.y);
            float v1B = fmaf(-RELAX, tB, a1rB);
            float z1B = fminf(v1B, up1);
            float u1B = fmaf(2.0f, z1B, -v1B);
            float ddlB = fmaf(-2.0f * RHO, u1B, yp2B);
            ddlB = fmaf(RHO, av2B, ddlB);
            ddlB = fmaf(-RHO, av3B, ddlB);
            if (hf == 0) sddpool[ITEM_OFF + (p ^ 1) * 64 + ddoff] = ddlB;

            // ---- trailing (off next critical path) ----
            float sA = fmaf(RHO, av2A, fmaf(RHO, av3A, mpt2));
            hsuA = sA * hirs;
            a1rA = fmaf(-RELAX, z1A, v1A);
            float a2rA = fmaxf(vnA.f.x, omr * vnA.f.x);
            float a3rA = fmaxf(vnA.f.y, omr * vnA.f.y);
            A23A = pack2(a2rA, a3rA);
            XpA = fma2(R2v, XTA, mul2(OMR2, XpA));

            float sB = fmaf(RHO, av2B, fmaf(RHO, av3B, mpt2));
            hsuB = sB * hirs;
            a1rB = fmaf(-RELAX, z1B, v1B);
            float a2rB = fmaxf(vnB.f.x, omr * vnB.f.x);
            float a3rB = fmaxf(vnB.f.y, omr * vnB.f.y);
            A23B = pack2(a2rB, a3rB);
            XpB = fma2(R2v, XTB, mul2(OMR2, XpB));
        }
        if (hf == 0) {
            F2U xa; xa.u = XpA;
            F2U xb; xb.u = XpB;
            out[bA * N + j] = xa.f.x - xa.f.y;
            out[bB * N + j] = xb.f.x - xb.f.y;
        }
    } else {
        // warp 8: lanes 0-15 -> item A scalar row, lanes 16-31 -> item B
        const int li = l & 15, itm = l >> 4;
        const int base = itm ? ITEM_OFF : 0;
        float4 qa = ((const float4*)sq)[li];
        float4 qb = ((const float4*)sq)[16 + li];
        float Q1v = sQ1;
        float b0v = bvec[0];
        float c2 = 0.f, Y0 = 0.f, z0 = 0.f;
#pragma unroll 2
        for (int it = 0; it < NITERS; it++) {
            const int p = it & 1;
            __syncthreads();
            const float4* dA = (const float4*)(sddpool + base + DD_A(p));
            const float4* dB = (const float4*)(sddpool + base + DD_B(p));
            float4 da = dA[li], db = dB[li];
            float r = qa.x * da.x + qa.y * da.y + qa.z * da.z + qa.w * da.w
                    + qb.x * db.x + qb.y * db.y + qb.z * db.z + qb.w * db.w;
            r += __shfl_xor_sync(0xffffffffu, r, 8);
            r += __shfl_xor_sync(0xffffffffu, r, 4);
            r += __shfl_xor_sync(0xffffffffu, r, 2);
            r += __shfl_xor_sync(0xffffffffu, r, 1);
            float zt0 = fmaf(c2, Q1v, r);
            float zr0 = fmaf(omr, z0, RELAX * zt0);
            Y0 = Y0 + zr0 - b0v;
            z0 = b0v;                        // clip(.., b0, b0) == b0
            c2 = 2.0f * RHO * (b0v - Y0);
            if (li == 0) c2buf[2 * (p ^ 1) + itm] = c2;
        }
    }
}

// ---------------- launcher ----------------
extern "C" void kernel_launch(void* const* d_in, const int* in_sizes, int n_in,
                              void* d_out, int out_size) {
    const float* X    = (const float*)d_in[0];
    const float* V    = (const float*)d_in[1];
    const float* beta = (const float*)d_in[2];
    const float* thE  = (const float*)d_in[3];
    const float* thD  = (const float*)d_in[4];
    const float* lg1  = (const float*)d_in[5];
    const float* lg2  = (const float*)d_in[6];
    const float* bvec = (const float*)d_in[8];
    const float* hvec = (const float*)d_in[10];
    float* out = (float*)d_out;

    mvo_kernel<<<BATCH / 2, 288>>>(X, V, beta, thE, thD, lg1, lg2, bvec, hvec, out);
}